// round 11
// baseline (speedup 1.0000x reference)
#include <cuda_runtime.h>
#include <cuda_bf16.h>
#include <cstdint>
#include <cstddef>

// Problem constants
#define BATCH 4
#define CC    256
#define HH_   96
#define WW_   96
#define HW    (HH_ * WW_)        // 9216
#define NPIX  (BATCH * HW)       // 36864
#define NK    33

// ---------------- device scratch ----------------
__device__ __nv_bfloat16 g_MtHi[CC * CC];
__device__ __nv_bfloat16 g_MtLo[CC * CC];
__device__ float g_v[CC];
__device__ float g_G[(size_t)BATCH * CC * HW];
__device__ float g_beta[NPIX];
__device__ float g_part[(size_t)2 * NK * NPIX];                    // 9.7MB
__device__ __align__(16) __nv_bfloat16 g_FtHi[(size_t)CC * NPIX]; // 18.9MB
__device__ __align__(16) __nv_bfloat16 g_FtLo[(size_t)CC * NPIX]; // 18.9MB

// ---------------- star offsets ----------------
__host__ __device__ constexpr int offA(int k) {
    if (k == 0) return 0;
    int s = (k - 1) / 8 + 1, r = (k - 1) % 8;
    int a = (r < 3) ? -1 : (r < 5 ? 0 : 1);
    return a * s;
}
__host__ __device__ constexpr int offB(int k) {
    if (k == 0) return 0;
    int s = (k - 1) / 8 + 1, r = (k - 1) % 8;
    int b = (r < 3) ? (r - 1) : (r == 3 ? -1 : (r == 4 ? 1 : r - 6));
    return b * s;
}

// ---------------- helpers ----------------
__device__ __forceinline__ uint32_t smem_u32(const void* p) {
    uint32_t a;
    asm("{ .reg .u64 t; cvta.to.shared.u64 t, %1; cvt.u32.u64 %0, t; }" : "=r"(a) : "l"(p));
    return a;
}
__device__ __forceinline__ void ldmx4(uint32_t* r, uint32_t a) {
    asm volatile("ldmatrix.sync.aligned.m8n8.x4.shared.b16 {%0,%1,%2,%3}, [%4];"
                 : "=r"(r[0]), "=r"(r[1]), "=r"(r[2]), "=r"(r[3]) : "r"(a));
}
__device__ __forceinline__ void ldmx4t(uint32_t* r, uint32_t a) {
    asm volatile("ldmatrix.sync.aligned.m8n8.x4.trans.shared.b16 {%0,%1,%2,%3}, [%4];"
                 : "=r"(r[0]), "=r"(r[1]), "=r"(r[2]), "=r"(r[3]) : "r"(a));
}
#define MMA16816(acc, a, b0, b1)                                              \
    asm volatile("mma.sync.aligned.m16n8k16.row.col.f32.bf16.bf16.f32 "       \
                 "{%0,%1,%2,%3},{%4,%5,%6,%7},{%8,%9},{%0,%1,%2,%3};"         \
                 : "+f"((acc)[0]), "+f"((acc)[1]), "+f"((acc)[2]), "+f"((acc)[3]) \
                 : "r"((a)[0]), "r"((a)[1]), "r"((a)[2]), "r"((a)[3]),        \
                   "r"(b0), "r"(b1))

__device__ __forceinline__ uint32_t packHi(float x, float y) {
    __nv_bfloat162 h = __floats2bfloat162_rn(x, y);
    return *reinterpret_cast<uint32_t*>(&h);
}
__device__ __forceinline__ uint32_t packLo(float x, float y, uint32_t hpack) {
    __nv_bfloat162 h = *reinterpret_cast<__nv_bfloat162*>(&hpack);
    __nv_bfloat162 l = __floats2bfloat162_rn(x - __bfloat162float(h.x),
                                             y - __bfloat162float(h.y));
    return *reinterpret_cast<uint32_t*>(&l);
}
__device__ __forceinline__ float2 bfsum2(uint32_t h, uint32_t l) {
    __nv_bfloat162 hh = *reinterpret_cast<__nv_bfloat162*>(&h);
    __nv_bfloat162 ll = *reinterpret_cast<__nv_bfloat162*>(&l);
    return make_float2(__bfloat162float(hh.x) + __bfloat162float(ll.x),
                       __bfloat162float(hh.y) + __bfloat162float(ll.y));
}

// ================= Kernel A: Mt = Wg^T Wf, split to bf16 hi/lo ================
__global__ void kMt(const float* __restrict__ Wf, const float* __restrict__ Wg) {
    __shared__ float gs[32][16];
    __shared__ float fs[32][16];
    const int tx = threadIdx.x, ty = threadIdx.y;
    const int t  = ty * 16 + tx;
    const int c1b = blockIdx.y * 16, c2b = blockIdx.x * 16;
    float acc = 0.f;
    for (int o0 = 0; o0 < CC; o0 += 32) {
        #pragma unroll
        for (int j = 0; j < 2; j++) {
            int i = t + j * 256;
            int r = i >> 4, q = i & 15;
            gs[r][q] = Wg[(o0 + r) * CC + c1b + q];
            fs[r][q] = Wf[(o0 + r) * CC + c2b + q];
        }
        __syncthreads();
        #pragma unroll
        for (int o = 0; o < 32; o++) acc += gs[o][ty] * fs[o][tx];
        __syncthreads();
    }
    __nv_bfloat16 hi = __float2bfloat16_rn(acc);
    __nv_bfloat16 lo = __float2bfloat16_rn(acc - __bfloat162float(hi));
    g_MtHi[(c1b + ty) * CC + (c2b + tx)] = hi;
    g_MtLo[(c1b + ty) * CC + (c2b + tx)] = lo;
}

// ================= Kernel V: v[c] = sum_o Wf[o,c]*bg[o] ========================
__global__ void kV(const float* __restrict__ Wf, const float* __restrict__ bg) {
    __shared__ float bgs[CC];
    const int c = threadIdx.x;
    bgs[c] = bg[c];
    __syncthreads();
    float acc = 0.f;
    #pragma unroll 8
    for (int o = 0; o < CC; o++) acc += Wf[o * CC + c] * bgs[o];
    g_v[c] = acc;
}

// ================= Kernel Conv: Ft -> bf16 hi/lo planes ========================
// Each thread: 8 elements (2 float4 reads -> 1 uint4 hi + 1 uint4 lo writes).
__global__ void __launch_bounds__(256) kConv(const float* __restrict__ Ft) {
    const size_t i8 = (size_t)blockIdx.x * 256 + threadIdx.x;
    const float4 f0 = *((const float4*)Ft + i8 * 2);
    const float4 f1 = *((const float4*)Ft + i8 * 2 + 1);
    uint32_t h0 = packHi(f0.x, f0.y), h1 = packHi(f0.z, f0.w);
    uint32_t h2 = packHi(f1.x, f1.y), h3 = packHi(f1.z, f1.w);
    uint32_t l0 = packLo(f0.x, f0.y, h0), l1 = packLo(f0.z, f0.w, h1);
    uint32_t l2 = packLo(f1.x, f1.y, h2), l3 = packLo(f1.z, f1.w, h3);
    ((uint4*)g_FtHi)[i8] = make_uint4(h0, h1, h2, h3);
    ((uint4*)g_FtLo)[i8] = make_uint4(l0, l1, l2, l3);
}

// ================= Kernel G: HMMA bf16-split GEMM + fused beta =================
// B operand pre-converted to bf16 (g_FtHi/g_FtLo): load loop is pure copies.
// Software-pipelined: gmem loads for chunk kc+1 issued before compute of kc.
#define SMV   0
#define SMAH  1024
#define SMAL  (SMAH + 128 * 80)      // 11264
#define SMBH  (SMAL + 128 * 80)      // 21504
#define SMBL  (SMBH + 8192)          // 29696
#define SMTOT (SMBL + 8192)          // 37888

__global__ void __launch_bounds__(256) kG() {
    __shared__ __align__(16) char sm[SMTOT];
    const uint32_t sb = smem_u32(sm);
    const int t = threadIdx.x;
    const int lane = t & 31, wid = t >> 5;
    const int wm = wid & 1, wn = wid >> 1;          // warp 64(M) x 32(N)

    const int b  = blockIdx.z;
    const int p0 = blockIdx.x * 128;
    const int m0 = blockIdx.y * 128;
    const bool doBeta = (blockIdx.y == 0);
    const __nv_bfloat16* FhB = g_FtHi + (size_t)b * CC * HW + p0;
    const __nv_bfloat16* FlB = g_FtLo + (size_t)b * CC * HW + p0;

    float* vs = (float*)(sm + SMV);
    vs[t] = g_v[t];

    float acc[4][4][4];
    #pragma unroll
    for (int i = 0; i < 4; i++)
        #pragma unroll
        for (int j = 0; j < 4; j++)
            #pragma unroll
            for (int r = 0; r < 4; r++) acc[i][j][r] = 0.f;
    float bacc[16];
    #pragma unroll
    for (int j = 0; j < 16; j++) bacc[j] = 0.f;

    const int arow = t >> 1;
    const int kq   = t >> 3;
    const int nslt = t & 7;

    // ---- register prefetch buffers ----
    uint4 pah[2], pal[2];        // A hi/lo
    uint4 pbh[2], pbl[2];        // B hi/lo (8 bf16 px each)

#define LOAD_CHUNK(k0)                                                          \
    { _Pragma("unroll")                                                         \
      for (int j = 0; j < 2; j++) {                                             \
          const int ch = (t & 1) * 2 + j;                                       \
          const size_t src = (size_t)(m0 + arow) * (CC * 2) + (size_t)(k0) * 2 + ch * 16; \
          pah[j] = *(const uint4*)((const char*)g_MtHi + src);                  \
          pal[j] = *(const uint4*)((const char*)g_MtLo + src);                  \
      }                                                                         \
      { const __nv_bfloat16* sH = FhB + (size_t)((k0) + kq) * HW + nslt * 16;   \
        const __nv_bfloat16* sL = FlB + (size_t)((k0) + kq) * HW + nslt * 16;   \
        pbh[0] = *(const uint4*)(sH);     pbh[1] = *(const uint4*)(sH + 8);     \
        pbl[0] = *(const uint4*)(sL);     pbl[1] = *(const uint4*)(sL + 8);     \
      } }

    LOAD_CHUNK(0);

    for (int kc = 0; kc < 8; kc++) {
        const int k0 = kc * 32;
        __syncthreads();                          // previous compute done with smem
        // ---- store A from regs ----
        #pragma unroll
        for (int j = 0; j < 2; j++) {
            const int ch = (t & 1) * 2 + j;
            *(uint4*)(sm + SMAH + arow * 80 + ch * 16) = pah[j];
            *(uint4*)(sm + SMAL + arow * 80 + ch * 16) = pal[j];
        }
        // ---- store B from regs (already bf16), beta FMA from hi+lo ----
        {
            const float vk = vs[k0 + kq];
            #pragma unroll
            for (int c = 0; c < 2; c++) {
                const int ch = ((nslt * 2 + c) ^ (kq & 7));
                *(uint4*)(sm + SMBH + kq * 256 + ch * 16) = pbh[c];
                *(uint4*)(sm + SMBL + kq * 256 + ch * 16) = pbl[c];
                if (doBeta) {
                    float2 v0 = bfsum2(pbh[c].x, pbl[c].x);
                    float2 v1 = bfsum2(pbh[c].y, pbl[c].y);
                    float2 v2 = bfsum2(pbh[c].z, pbl[c].z);
                    float2 v3 = bfsum2(pbh[c].w, pbl[c].w);
                    bacc[c * 8 + 0] = fmaf(vk, v0.x, bacc[c * 8 + 0]);
                    bacc[c * 8 + 1] = fmaf(vk, v0.y, bacc[c * 8 + 1]);
                    bacc[c * 8 + 2] = fmaf(vk, v1.x, bacc[c * 8 + 2]);
                    bacc[c * 8 + 3] = fmaf(vk, v1.y, bacc[c * 8 + 3]);
                    bacc[c * 8 + 4] = fmaf(vk, v2.x, bacc[c * 8 + 4]);
                    bacc[c * 8 + 5] = fmaf(vk, v2.y, bacc[c * 8 + 5]);
                    bacc[c * 8 + 6] = fmaf(vk, v3.x, bacc[c * 8 + 6]);
                    bacc[c * 8 + 7] = fmaf(vk, v3.y, bacc[c * 8 + 7]);
                }
            }
        }
        __syncthreads();                          // smem ready for compute
        if (kc + 1 < 8) LOAD_CHUNK(k0 + 32);      // prefetch next (hidden by MMA)
        // ---- compute: 2 k16 steps x 3 terms ----
        #pragma unroll
        for (int ks = 0; ks < 2; ks++) {
            const int kk = ks * 16;
            const int aRow = wm * 64 + (lane & 15);
            const int aKb  = kk * 2 + (lane & 16);
            const int bK   = kk + (lane & 15);
            uint32_t FA[4][4], FB[2][4], FB2[2][4];
            #pragma unroll
            for (int mi = 0; mi < 4; mi++)
                ldmx4(FA[mi], sb + SMAH + (aRow + mi * 16) * 80 + aKb);
            #pragma unroll
            for (int p = 0; p < 2; p++) {
                const int nb = wn * 64 + p * 32 + (lane & 16);
                const int ch = ((nb >> 4) ^ (bK & 7));
                ldmx4t(FB[p], sb + SMBH + bK * 256 + (ch << 4));
            }
            #pragma unroll
            for (int mi = 0; mi < 4; mi++)
                #pragma unroll
                for (int p = 0; p < 2; p++) {
                    MMA16816(acc[mi][p * 2 + 0], FA[mi], FB[p][0], FB[p][1]);
                    MMA16816(acc[mi][p * 2 + 1], FA[mi], FB[p][2], FB[p][3]);
                }
            #pragma unroll
            for (int p = 0; p < 2; p++) {
                const int nb = wn * 64 + p * 32 + (lane & 16);
                const int ch = ((nb >> 4) ^ (bK & 7));
                ldmx4t(FB2[p], sb + SMBL + bK * 256 + (ch << 4));
            }
            #pragma unroll
            for (int mi = 0; mi < 4; mi++)
                #pragma unroll
                for (int p = 0; p < 2; p++) {
                    MMA16816(acc[mi][p * 2 + 0], FA[mi], FB2[p][0], FB2[p][1]);
                    MMA16816(acc[mi][p * 2 + 1], FA[mi], FB2[p][2], FB2[p][3]);
                }
            #pragma unroll
            for (int mi = 0; mi < 4; mi++)
                ldmx4(FA[mi], sb + SMAL + (aRow + mi * 16) * 80 + aKb);
            #pragma unroll
            for (int mi = 0; mi < 4; mi++)
                #pragma unroll
                for (int p = 0; p < 2; p++) {
                    MMA16816(acc[mi][p * 2 + 0], FA[mi], FB[p][0], FB[p][1]);
                    MMA16816(acc[mi][p * 2 + 1], FA[mi], FB[p][2], FB[p][3]);
                }
        }
    }
#undef LOAD_CHUNK

    {
        float* GB = g_G + (size_t)b * CC * HW + p0;
        const int g = lane >> 2, t4 = lane & 3;
        #pragma unroll
        for (int mi = 0; mi < 4; mi++) {
            const int row = m0 + wm * 64 + mi * 16 + g;
            #pragma unroll
            for (int nb = 0; nb < 4; nb++) {
                const int px = wn * 32 + nb * 8 + t4 * 2;
                *(float2*)(GB + (size_t)row * HW + px) =
                    make_float2(acc[mi][nb][0], acc[mi][nb][1]);
                *(float2*)(GB + (size_t)(row + 8) * HW + px) =
                    make_float2(acc[mi][nb][2], acc[mi][nb][3]);
            }
        }
    }

    if (doBeta) {
        __syncthreads();
        float* bsm = (float*)(sm + SMAH);
        #pragma unroll
        for (int j = 0; j < 16; j += 4)
            *(float4*)(bsm + t * 16 + j) =
                make_float4(bacc[j], bacc[j + 1], bacc[j + 2], bacc[j + 3]);
        __syncthreads();
        if (t < 128) {
            const int slot = t >> 4, jj = t & 15;
            float s = 0.f;
            #pragma unroll 8
            for (int kg = 0; kg < 32; kg++)
                s += bsm[(kg * 8 + slot) * 16 + jj];
            g_beta[b * HW + p0 + t] = s;
        }
    }
}

// ============ shared tile geometry for the attention kernels ============
#define TW   32
#define TH   8
#define HALO 4
#define SW   (TW + 2 * HALO)   // 40
#define SH   (TH + 2 * HALO)   // 16
#define SN   (SH * SW)         // 640
#define CH   4
#define SNC  (SN * CH)         // 2560
#define NGH  (128 / CH)        // 32 groups per half

#define STAGE_MAP()                                                     \
    int  soff[10];                                                      \
    bool svld[10];                                                      \
    _Pragma("unroll")                                                   \
    for (int j = 0; j < 10; j++) {                                      \
        int idx = t + j * 256;                                          \
        int q = idx / SN, i = idx - q * SN;                             \
        int r = i / SW, cc = i - r * SW;                                \
        int hh = h0 - HALO + r, ww = w0 - HALO + cc;                    \
        svld[j] = ((unsigned)hh < HH_) && ((unsigned)ww < WW_);         \
        soff[j] = q * HW + hh * WW_ + ww;                               \
    }                                                                   \
    float stg[10];

#define GLOAD(src)                                             \
    { _Pragma("unroll")                                        \
      for (int j = 0; j < 10; j++)                             \
          stg[j] = svld[j] ? (src)[soff[j]] : 0.f; }
#define GSTORE(dst)                                            \
    { _Pragma("unroll")                                        \
      for (int j = 0; j < 10; j++)                             \
          (dst)[t + j * 256] = stg[j]; }

// ====== Kernel Attn1: partial logits over one 128-channel half ======
__global__ void __launch_bounds__(256, 2) kAttn1(const float* __restrict__ Fte) {
    __shared__ float Sh[2][SNC];
    const int t  = threadIdx.x;
    const int tx = t & 31, ty = t >> 5;
    const int zz = blockIdx.z;
    const int b = zz >> 1, half = zz & 1;
    const int w0 = blockIdx.x * TW, h0 = blockIdx.y * TH;
    const int h = h0 + ty, w = w0 + tx;
    const int pix = h * WW_ + w;
    const size_t plane = (size_t)b * CC * HW + (size_t)half * 128 * HW;

    STAGE_MAP();

    float lg[NK];
    #pragma unroll
    for (int k = 0; k < NK; k++) lg[k] = 0.f;

    const float* Gb = g_G + plane;
    const float* Fb = Fte + plane;
    GLOAD(Gb);
    GSTORE(Sh[0]);
    GLOAD(Gb + CH * HW);
    float fe[CH], fen[CH];
    #pragma unroll
    for (int cc = 0; cc < CH; cc++) fe[cc] = Fb[(size_t)cc * HW + pix];
    for (int g = 0; g < NGH; g++) {
        const int buf = g & 1;
        __syncthreads();
        if (g + 1 < NGH) GSTORE(Sh[buf ^ 1]);
        if (g + 2 < NGH) GLOAD(Gb + (size_t)(g + 2) * CH * HW);
        #pragma unroll
        for (int cc = 0; cc < CH; cc++)
            fen[cc] = (g + 1 < NGH) ? Fb[(size_t)((g + 1) * CH + cc) * HW + pix] : 0.f;
        const float* S = Sh[buf];
        const int sbase = (ty + HALO) * SW + (tx + HALO);
        #pragma unroll
        for (int cc = 0; cc < CH; cc++) {
            const float fc = fe[cc];
            const float* Sc = S + cc * SN;
            #pragma unroll
            for (int k = 0; k < NK; k++)
                lg[k] += fc * Sc[sbase + offA(k) * SW + offB(k)];
        }
        #pragma unroll
        for (int cc = 0; cc < CH; cc++) fe[cc] = fen[cc];
    }

    float* dst = g_part + (size_t)half * NK * NPIX + b * HW + pix;
    #pragma unroll
    for (int k = 0; k < NK; k++) dst[(size_t)k * NPIX] = lg[k];
}

// ====== Kernel Attn2: combine + softmax + aggregate one half ======
__global__ void __launch_bounds__(256, 2) kAttn2(const float* __restrict__ Ft,
                                                 float* __restrict__ out) {
    __shared__ float Sh[2][SNC];
    const int t  = threadIdx.x;
    const int tx = t & 31, ty = t >> 5;
    const int zz = blockIdx.z;
    const int b = zz >> 1, half = zz & 1;
    const int w0 = blockIdx.x * TW, h0 = blockIdx.y * TH;
    const int h = h0 + ty, w = w0 + tx;
    const int pix = h * WW_ + w;
    const size_t plane = (size_t)b * CC * HW + (size_t)half * 128 * HW;
    const int sbase = (ty + HALO) * SW + (tx + HALO);

    STAGE_MAP();

    // beta halo + validity mask
    #pragma unroll
    for (int j = 0; j < 3; j++) {
        int i = t + j * 256;
        if (i < SN) {
            int r = i / SW, cc = i - r * SW;
            int hh = h0 - HALO + r, ww = w0 - HALO + cc;
            bool v = ((unsigned)hh < HH_) && ((unsigned)ww < WW_);
            Sh[0][i] = v ? g_beta[b * HW + hh * WW_ + ww] : 0.f;
        }
    }
    __syncthreads();
    float lg[NK];
    #pragma unroll
    for (int k = 0; k < NK; k++) {
        const int a = offA(k), bo = offB(k);
        const bool valid = ((unsigned)(h + a) < HH_) && ((unsigned)(w + bo) < WW_);
        lg[k] = valid ? Sh[0][sbase + a * SW + bo] : -1e30f;
    }
    __syncthreads();

    // combine partial halves
    const float* pP = g_part + b * HW + pix;
    #pragma unroll
    for (int k = 0; k < NK; k++)
        lg[k] += pP[(size_t)k * NPIX] + pP[(size_t)(NK + k) * NPIX];

    // softmax over 33
    float m = lg[0];
    #pragma unroll
    for (int k = 1; k < NK; k++) m = fmaxf(m, lg[k]);
    float s = 0.f;
    #pragma unroll
    for (int k = 0; k < NK; k++) { lg[k] = expf(lg[k] - m); s += lg[k]; }
    const float inv = 1.0f / s;
    #pragma unroll
    for (int k = 0; k < NK; k++) lg[k] *= inv;

    // aggregate this half's 128 channels
    const float* Fa = Ft + plane;
    float*       Ob = out + plane;
    GLOAD(Fa);
    GSTORE(Sh[0]);
    GLOAD(Fa + CH * HW);
    for (int g = 0; g < NGH; g++) {
        const int buf = g & 1;
        __syncthreads();
        if (g + 1 < NGH) GSTORE(Sh[buf ^ 1]);
        if (g + 2 < NGH) GLOAD(Fa + (size_t)(g + 2) * CH * HW);
        const float* S = Sh[buf];
        #pragma unroll
        for (int cc = 0; cc < CH; cc++) {
            const float* Sc = S + cc * SN;
            float acc = 0.f;
            #pragma unroll
            for (int k = 0; k < NK; k++)
                acc += lg[k] * Sc[sbase + offA(k) * SW + offB(k)];
            Ob[(size_t)(g * CH + cc) * HW + pix] = acc;
        }
    }
}

// =================================== launch ======================================
extern "C" void kernel_launch(void* const* d_in, const int* in_sizes, int n_in,
                              void* d_out, int out_size) {
    const float* Ft  = (const float*)d_in[0];
    const float* Fte = (const float*)d_in[1];
    const float* Wf  = (const float*)d_in[2];
    const float* Wg  = (const float*)d_in[4];
    const float* bg  = (const float*)d_in[5];
    float* out = (float*)d_out;

    kMt<<<dim3(16, 16), dim3(16, 16)>>>(Wf, Wg);
    kV<<<1, 256>>>(Wf, bg);
    kConv<<<(CC * NPIX) / (256 * 8), 256>>>(Ft);
    kG<<<dim3(HW / 128, 2, BATCH), 256>>>();
    kAttn1<<<dim3(WW_ / TW, HH_ / TH, BATCH * 2), 256>>>(Fte);
    kAttn2<<<dim3(WW_ / TW, HH_ / TH, BATCH * 2), 256>>>(Ft, out);
}